// round 10
// baseline (speedup 1.0000x reference)
#include <cuda_runtime.h>
#include <cuda_fp16.h>
#include <math.h>

#define BATCH 16
#define SEQ   512
#define EMB   768
#define HEADS 12
#define HDIM  64
#define ROWS  (BATCH*SEQ)          // 8192
#define BHN   (BATCH*HEADS)        // 192

// fp16 staging globals
__device__ __half g_inph[ROWS*EMB];          // [m][k]
__device__ __half g_Wh[3*EMB*EMB];           // [w][k][n]
__device__ __half g_Qh[BHN*SEQ*HDIM];        // [bh][s][d], pre-scaled 0.125*log2(e)
__device__ __half g_Kh[BHN*SEQ*HDIM];        // [bh][j][d]  compacted keys
__device__ __half g_Vh[BHN*SEQ*HDIM];        // [bh][j][d]  compacted keys
__device__ int    g_srcs[BATCH*SEQ];
__device__ int    g_nk[BATCH];

// scheduler state
#define FO_CVTA 0
#define FO_CVTW 64
#define FO_CMP  82
#define FO_Q    98
#define FO_K    482
#define FO_V    866
#define NFLAGS  1250
#define NITEMS  2018                 // 1250 producers + 768 attn
__device__ int g_ctr;
__device__ int g_flags[NFLAGS];

// ---------------------------------------------------------------------------
// low-level helpers
// ---------------------------------------------------------------------------
__device__ __forceinline__ void mma16(float c[4],
                                      unsigned a0, unsigned a1, unsigned a2, unsigned a3,
                                      unsigned b0, unsigned b1) {
    asm volatile(
        "mma.sync.aligned.m16n8k16.row.col.f32.f16.f16.f32 "
        "{%0,%1,%2,%3}, {%4,%5,%6,%7}, {%8,%9}, {%0,%1,%2,%3};"
        : "+f"(c[0]), "+f"(c[1]), "+f"(c[2]), "+f"(c[3])
        : "r"(a0), "r"(a1), "r"(a2), "r"(a3), "r"(b0), "r"(b1));
}
__device__ __forceinline__ void ldm4(unsigned& r0, unsigned& r1,
                                     unsigned& r2, unsigned& r3, unsigned a) {
    asm volatile("ldmatrix.sync.aligned.m8n8.x4.shared.b16 {%0,%1,%2,%3}, [%4];"
                 : "=r"(r0), "=r"(r1), "=r"(r2), "=r"(r3) : "r"(a));
}
__device__ __forceinline__ void ldm4t(unsigned& r0, unsigned& r1,
                                      unsigned& r2, unsigned& r3, unsigned a) {
    asm volatile("ldmatrix.sync.aligned.m8n8.x4.trans.shared.b16 {%0,%1,%2,%3}, [%4];"
                 : "=r"(r0), "=r"(r1), "=r"(r2), "=r"(r3) : "r"(a));
}
__device__ __forceinline__ unsigned pkh2(float lo, float hi) {
    unsigned r;
    asm("cvt.rn.f16x2.f32 %0, %1, %2;" : "=r"(r) : "f"(hi), "f"(lo));
    return r;
}
__device__ __forceinline__ float ex2(float x) {
    float r;
    asm("ex2.approx.ftz.f32 %0, %1;" : "=f"(r) : "f"(x));
    return r;
}
__device__ __forceinline__ unsigned smem_u32(const void* p) {
    unsigned a;
    asm("{.reg .u64 t; cvta.to.shared.u64 t, %1; cvt.u32.u64 %0, t;}"
        : "=r"(a) : "l"(p));
    return a;
}
__device__ __forceinline__ void cpa16(unsigned dst, const void* src) {
    asm volatile("cp.async.ca.shared.global [%0], [%1], 16;" :: "r"(dst), "l"(src));
}
#define CP_COMMIT() asm volatile("cp.async.commit_group;" ::: "memory")
#define CP_WAIT(N)  asm volatile("cp.async.wait_group %0;" :: "n"(N) : "memory")

__device__ __forceinline__ int ldacq(const int* p) {
    int v;
    asm volatile("ld.global.acquire.gpu.b32 %0, [%1];" : "=r"(v) : "l"(p));
    return v;
}
__device__ __forceinline__ void wait1(const int* f) {
    while (!ldacq(f)) __nanosleep(64);
}
__device__ __forceinline__ void setflag(int* f) {
    __threadfence();
    asm volatile("st.global.release.gpu.b32 [%0], %1;" :: "l"(f), "r"(1) : "memory");
}

// ---------------------------------------------------------------------------
// item bodies
// ---------------------------------------------------------------------------
__device__ void do_cvtA(int i, const float* __restrict__ inp) {
    const int tid = threadIdx.x;
    const float4* s4 = reinterpret_cast<const float4*>(inp) + (long)i*24576;
    __half2* o2 = reinterpret_cast<__half2*>(g_inph) + (long)i*49152;
    #pragma unroll 4
    for (int j = 0; j < 96; j++) {
        int idx = tid + j*256;
        float4 v = s4[idx];
        o2[idx*2]   = __floats2half2_rn(v.x, v.y);
        o2[idx*2+1] = __floats2half2_rn(v.z, v.w);
    }
}

__device__ void do_cvtW(int r, const float* __restrict__ Wq,
                        const float* __restrict__ Wk, const float* __restrict__ Wv) {
    const int tid = threadIdx.x;
    const int w = r / 6, nb = r % 6;
    const float* W = (w == 0) ? Wq : (w == 1) ? Wk : Wv;
    __half* O = g_Wh + (long)w*EMB*EMB;
    #pragma unroll 4
    for (int j = 0; j < 96; j++) {
        int flat = tid + j*256;
        int row = flat >> 5, c4 = flat & 31;
        float4 v = *reinterpret_cast<const float4*>(&W[row*EMB + nb*128 + c4*4]);
        __half2* o = reinterpret_cast<__half2*>(&O[row*EMB + nb*128 + c4*4]);
        o[0] = __floats2half2_rn(v.x, v.y);
        o[1] = __floats2half2_rn(v.z, v.w);
    }
}

__device__ void do_cmp(int b, const float* __restrict__ mask) {
    const int tid = threadIdx.x;
    __shared__ int sc[512];
    int f0 = (mask[b*512 + tid]       == 0.0f) ? 1 : 0;
    int f1 = (mask[b*512 + 256 + tid] == 0.0f) ? 1 : 0;
    sc[tid] = f0; sc[tid + 256] = f1;
    __syncthreads();
    for (int off = 1; off < 512; off <<= 1) {
        int i0 = tid, i1 = tid + 256;
        int v0 = sc[i0] + ((i0 >= off) ? sc[i0 - off] : 0);
        int v1 = sc[i1] + ((i1 >= off) ? sc[i1 - off] : 0);
        __syncthreads();
        sc[i0] = v0; sc[i1] = v1;
        __syncthreads();
    }
    int nk = sc[511];
    if (f0) g_srcs[b*512 + sc[tid] - 1]       = b*512 + tid;
    if (f1) g_srcs[b*512 + sc[tid + 256] - 1] = b*512 + 256 + tid;
    if (tid >= nk)       g_srcs[b*512 + tid]       = b*512;
    if (tid + 256 >= nk) g_srcs[b*512 + 256 + tid] = b*512;
    if (tid == 0) g_nk[b] = nk;
}

// ---- projection item: 128x128 tile of Q (z=0) / K (z=1) / V (z=2) ----
#define AH    72
#define ABUFH (128*AH)             // 9216 halves
#define BHS   136
#define BBUFH (64*BHS)             // 8704 halves
#define PROJ_SMEM ((2*ABUFH + 2*BBUFH)*2)   // 71680 B

__device__ void do_proj(int z, int qn, int yr, __half* smbase,
                        const float* __restrict__ bq, const float* __restrict__ bk,
                        const float* __restrict__ bv)
{
    const int tid  = threadIdx.x;
    const int lane = tid & 31;
    const int wid  = tid >> 5;
    const int wm = (wid & 1) * 64;
    const int wn = (wid >> 1) * 32;
    const int g  = lane >> 2;
    const int t  = lane & 3;
    const int l15  = lane & 15;
    const int l7   = lane & 7;
    const int hi16 = (lane >> 4) & 1;
    const int hi8  = (lane >> 3) & 1;

    int bb = 0, tt = 0, nkb = 0;
    // dependency waits
    if (tid == 0) {
        if (z == 0) {
            wait1(&g_flags[FO_CVTA + yr]);
            wait1(&g_flags[FO_CVTW + qn]);
        } else {
            int b = yr >> 2;
            wait1(&g_flags[FO_CMP + b]);
            wait1(&g_flags[FO_CVTW + z*6 + qn]);
            #pragma unroll
            for (int i = 0; i < 4; i++) wait1(&g_flags[FO_CVTA + b*4 + i]);
        }
    }
    __syncthreads();

    if (z > 0) {
        bb = yr >> 2; tt = yr & 3;
        nkb = g_nk[bb];
        if (tt*128 >= nkb) return;     // caller still sets the flag
    }

    const __half* Wp = g_Wh + (long)z*EMB*EMB;
    const float* bias = (z == 0) ? bq : (z == 1) ? bk : bv;
    const int n0 = qn * 128;

    __shared__ int s_idx[128];
    if (tid < 128)
        s_idx[tid] = (z == 0) ? (yr*128 + tid) : g_srcs[bb*512 + tt*128 + tid];
    __syncthreads();

    const unsigned sb = smem_u32(smbase);
    const unsigned abase = sb + ((wm + l15)*AH + hi16*8)*2;
    const unsigned bbase = sb + 2*ABUFH*2 + ((l7 + hi8*8)*BHS + wn + hi16*8)*2;

    float acc[4][4][4];
    #pragma unroll
    for (int mi = 0; mi < 4; mi++)
        #pragma unroll
        for (int nj = 0; nj < 4; nj++)
            #pragma unroll
            for (int c = 0; c < 4; c++) acc[mi][nj][c] = 0.0f;

    #define P_ISSUE(IT, BUF) { \
        _Pragma("unroll") for (int i = 0; i < 4; i++) { \
            int f = tid + i*256; int r = f >> 3; int c8 = f & 7; \
            cpa16(sb + ((BUF)*ABUFH + r*AH + c8*8)*2, \
                  g_inph + (long)s_idx[r]*EMB + (IT)*64 + c8*8); } \
        _Pragma("unroll") for (int i = 0; i < 4; i++) { \
            int f = tid + i*256; int r = f >> 4; int c8 = f & 15; \
            cpa16(sb + (2*ABUFH + (BUF)*BBUFH + r*BHS + c8*8)*2, \
                  Wp + ((IT)*64 + r)*EMB + n0 + c8*8); } \
        CP_COMMIT(); }

    P_ISSUE(0, 0);
    P_ISSUE(1, 1);

    for (int it = 0; it < 12; it++) {
        if (it < 10) CP_WAIT(1); else CP_WAIT(0);
        __syncthreads();

        const int buf = it & 1;
        const unsigned ab = abase + buf*ABUFH*2;
        const unsigned bb2 = bbase + buf*BBUFH*2;

        #pragma unroll
        for (int s = 0; s < 4; s++) {
            unsigned a[4][4];
            #pragma unroll
            for (int mi = 0; mi < 4; mi++)
                ldm4(a[mi][0], a[mi][1], a[mi][2], a[mi][3],
                     ab + (mi*16*AH + s*16)*2);
            unsigned b[4][2];
            #pragma unroll
            for (int p = 0; p < 2; p++) {
                unsigned r0, r1, r2, r3;
                ldm4t(r0, r1, r2, r3, bb2 + (s*16*BHS + p*16)*2);
                b[2*p][0] = r0; b[2*p][1] = r1;
                b[2*p+1][0] = r2; b[2*p+1][1] = r3;
            }
            #pragma unroll
            for (int mi = 0; mi < 4; mi++)
                #pragma unroll
                for (int nj = 0; nj < 4; nj++)
                    mma16(acc[mi][nj], a[mi][0], a[mi][1], a[mi][2], a[mi][3],
                          b[nj][0], b[nj][1]);
        }

        if (it + 2 < 12) {
            __syncthreads();
            P_ISSUE(it + 2, buf);
        }
    }
    #undef P_ISSUE

    if (z == 0) {
        const float qs = 0.18033688f;   // 0.125 * log2(e)
        #pragma unroll
        for (int mi = 0; mi < 4; mi++) {
            #pragma unroll
            for (int nj = 0; nj < 4; nj++) {
                #pragma unroll
                for (int c = 0; c < 4; c++) {
                    int row = yr*128 + wm + mi*16 + g + ((c >= 2) ? 8 : 0);
                    int n   = n0 + wn + nj*8 + 2*t + (c & 1);
                    int h = n >> 6, d = n & 63;
                    int b = row >> 9, s = row & 511;
                    float val = (acc[mi][nj][c] + bias[n]) * qs;
                    g_Qh[((long)(b*HEADS + h)*SEQ + s)*HDIM + d] = __float2half_rn(val);
                }
            }
        }
    } else {
        __half* outh = (z == 1) ? g_Kh : g_Vh;
        #pragma unroll
        for (int mi = 0; mi < 4; mi++) {
            #pragma unroll
            for (int nj = 0; nj < 4; nj++) {
                #pragma unroll
                for (int c = 0; c < 4; c++) {
                    int rloc = wm + mi*16 + g + ((c >= 2) ? 8 : 0);
                    int j = tt*128 + rloc;
                    if (j < nkb) {
                        int n = n0 + wn + nj*8 + 2*t + (c & 1);
                        int h = n >> 6, d = n & 63;
                        float val = acc[mi][nj][c] + bias[n];
                        outh[((long)(bb*HEADS + h)*SEQ + j)*HDIM + d] =
                            __float2half_rn(val);
                    }
                }
            }
        }
    }
}

// ---- attention item: (b, h, 128-query tile) over compacted keys ----
#define QH    72
#define QBUFH (128*QH)             // 9216
#define KH    72
#define KBUFH (64*KH)              // 4608
#define VH    72
#define VBUFH (64*VH)              // 4608

__device__ void do_attn(int rel, __half* smbase, float* __restrict__ out)
{
    const int b  = rel / 48;
    const int hr = rel % 48;
    const int h  = hr >> 2;
    const int qt = hr & 3;
    const int bh = b*HEADS + h;
    const int q0 = qt * 128;
    const int qn = h >> 1;
    const int tid  = threadIdx.x;
    const int lane = tid & 31;
    const int wid  = tid >> 5;
    const int wm = wid * 16;
    const int g  = lane >> 2;
    const int t  = lane & 3;
    const int l15  = lane & 15;
    const int l7   = lane & 7;
    const int hi16 = (lane >> 4) & 1;
    const int hi8  = (lane >> 3) & 1;

    if (tid == 0) {
        wait1(&g_flags[FO_CMP + b]);
        wait1(&g_flags[FO_Q + qn*64 + b*4 + qt]);
        #pragma unroll
        for (int i = 0; i < 4; i++) {
            wait1(&g_flags[FO_K + qn*64 + b*4 + i]);
            wait1(&g_flags[FO_V + qn*64 + b*4 + i]);
        }
    }
    __syncthreads();

    const int nk  = g_nk[b];
    const int nch = (nk + 63) >> 6;

    const unsigned sb = smem_u32(smbase);
    const __half* Qg = g_Qh + (long)bh*SEQ*HDIM + (long)q0*HDIM;
    const __half* Kg = g_Kh + (long)bh*SEQ*HDIM;
    const __half* Vg = g_Vh + (long)bh*SEQ*HDIM;

    const unsigned qbase = sb + ((wm + l15)*QH + hi16*8)*2;
    const unsigned kbase = sb + QBUFH*2 + ((l7 + hi16*8)*KH + hi8*8)*2;
    const unsigned vbase = sb + (QBUFH + 2*KBUFH)*2 + ((l7 + hi8*8)*VH + hi16*8)*2;

    #define A_ISSUE_KV(KC, BUF) { \
        _Pragma("unroll") for (int i = 0; i < 2; i++) { \
            int f = tid + i*256; int r = f >> 3; int c8 = f & 7; \
            cpa16(sb + (QBUFH + (BUF)*KBUFH + r*KH + c8*8)*2, \
                  Kg + ((KC)*64 + r)*HDIM + c8*8); } \
        _Pragma("unroll") for (int i = 0; i < 2; i++) { \
            int f = tid + i*256; int r = f >> 3; int c8 = f & 7; \
            cpa16(sb + (QBUFH + 2*KBUFH + (BUF)*VBUFH + r*VH + c8*8)*2, \
                  Vg + ((KC)*64 + r)*HDIM + c8*8); } \
        CP_COMMIT(); }

    {
        #pragma unroll
        for (int i = 0; i < 4; i++) {
            int f = tid + i*256; int r = f >> 3; int c8 = f & 7;
            cpa16(sb + (r*QH + c8*8)*2, Qg + r*HDIM + c8*8);
        }
        A_ISSUE_KV(0, 0);
        A_ISSUE_KV(1, 1);
    }

    float oacc[8][4];
    #pragma unroll
    for (int dj = 0; dj < 8; dj++)
        #pragma unroll
        for (int c = 0; c < 4; c++) oacc[dj][c] = 0.0f;
    float l0 = 0.0f, l1 = 0.0f;
    const unsigned FULL = 0xffffffffu;

    for (int kc = 0; kc < nch; kc++) {
        if (kc + 2 < nch) CP_WAIT(1); else CP_WAIT(0);
        __syncthreads();

        const int buf = kc & 1;
        const unsigned kb = kbase + buf*KBUFH*2;
        const unsigned vb = vbase + buf*VBUFH*2;

        float sacc[8][4];
        #pragma unroll
        for (int nj = 0; nj < 8; nj++)
            #pragma unroll
            for (int c = 0; c < 4; c++) sacc[nj][c] = 0.0f;

        #pragma unroll
        for (int s = 0; s < 4; s++) {
            unsigned a0, a1, a2, a3;
            ldm4(a0, a1, a2, a3, qbase + (s*16)*2);
            #pragma unroll
            for (int p = 0; p < 4; p++) {
                unsigned r0, r1, r2, r3;
                ldm4(r0, r1, r2, r3, kb + (p*16*KH + s*16)*2);
                mma16(sacc[2*p],   a0, a1, a2, a3, r0, r1);
                mma16(sacc[2*p+1], a0, a1, a2, a3, r2, r3);
            }
        }

        float rs0 = 0.0f, rs1 = 0.0f;
        if (kc + 1 == nch) {
            #pragma unroll
            for (int nj = 0; nj < 8; nj++) {
                int key = kc*64 + nj*8 + 2*t;
                float p0 = (key   < nk) ? ex2(sacc[nj][0]) : 0.0f;
                float p1 = (key+1 < nk) ? ex2(sacc[nj][1]) : 0.0f;
                float p2 = (key   < nk) ? ex2(sacc[nj][2]) : 0.0f;
                float p3 = (key+1 < nk) ? ex2(sacc[nj][3]) : 0.0f;
                sacc[nj][0] = p0; sacc[nj][1] = p1;
                sacc[nj][2] = p2; sacc[nj][3] = p3;
                rs0 += p0 + p1; rs1 += p2 + p3;
            }
        } else {
            #pragma unroll
            for (int nj = 0; nj < 8; nj++) {
                float p0 = ex2(sacc[nj][0]);
                float p1 = ex2(sacc[nj][1]);
                float p2 = ex2(sacc[nj][2]);
                float p3 = ex2(sacc[nj][3]);
                sacc[nj][0] = p0; sacc[nj][1] = p1;
                sacc[nj][2] = p2; sacc[nj][3] = p3;
                rs0 += p0 + p1; rs1 += p2 + p3;
            }
        }
        l0 += rs0;
        l1 += rs1;

        #pragma unroll
        for (int s = 0; s < 4; s++) {
            unsigned a0 = pkh2(sacc[2*s][0],   sacc[2*s][1]);
            unsigned a1 = pkh2(sacc[2*s][2],   sacc[2*s][3]);
            unsigned a2 = pkh2(sacc[2*s+1][0], sacc[2*s+1][1]);
            unsigned a3 = pkh2(sacc[2*s+1][2], sacc[2*s+1][3]);
            #pragma unroll
            for (int p = 0; p < 4; p++) {
                unsigned r0, r1, r2, r3;
                ldm4t(r0, r1, r2, r3, vb + (s*16*VH + p*16)*2);
                mma16(oacc[2*p],   a0, a1, a2, a3, r0, r1);
                mma16(oacc[2*p+1], a0, a1, a2, a3, r2, r3);
            }
        }

        if (kc + 2 < nch) {
            __syncthreads();
            A_ISSUE_KV(kc + 2, buf);
        }
    }
    #undef A_ISSUE_KV

    l0 += __shfl_xor_sync(FULL, l0, 1);
    l0 += __shfl_xor_sync(FULL, l0, 2);
    l1 += __shfl_xor_sync(FULL, l1, 1);
    l1 += __shfl_xor_sync(FULL, l1, 2);
    float inv0 = 1.0f / l0;
    float inv1 = 1.0f / l1;

    const int qa = q0 + wm + g;
    const int qb = qa + 8;
    #pragma unroll
    for (int dj = 0; dj < 8; dj++) {
        int d = h*HDIM + dj*8 + 2*t;
        out[(b*SEQ + qa)*EMB + d]     = oacc[dj][0] * inv0;
        out[(b*SEQ + qa)*EMB + d + 1] = oacc[dj][1] * inv0;
        out[(b*SEQ + qb)*EMB + d]     = oacc[dj][2] * inv1;
        out[(b*SEQ + qb)*EMB + d + 1] = oacc[dj][3] * inv1;
    }
}

// ---------------------------------------------------------------------------
// scheduler reset + persistent mega-kernel
// ---------------------------------------------------------------------------
__global__ __launch_bounds__(256) void zero_kernel() {
    int i = threadIdx.x;
    if (i == 0) g_ctr = 0;
    for (int j = i; j < NFLAGS; j += 256) g_flags[j] = 0;
}

__global__ __launch_bounds__(256, 2) void mega_kernel(
    const float* __restrict__ inp,  const float* __restrict__ mask,
    const float* __restrict__ Wq,   const float* __restrict__ bq,
    const float* __restrict__ Wk,   const float* __restrict__ bk,
    const float* __restrict__ Wv,   const float* __restrict__ bv,
    float* __restrict__ out)
{
    extern __shared__ __half sm[];
    __shared__ int s_item;

    for (;;) {
        __syncthreads();              // protect smem reuse across items
        if (threadIdx.x == 0) s_item = atomicAdd(&g_ctr, 1);
        __syncthreads();
        const int item = s_item;
        if (item >= NITEMS) break;

        if (item < 64) {
            do_cvtA(item, inp);
        } else if (item < 82) {
            do_cvtW(item - 64, Wq, Wk, Wv);
        } else if (item < 98) {
            do_cmp(item - 82, mask);
        } else if (item < 482) {
            int rel = item - 98;
            do_proj(0, rel / 64, rel % 64, sm, bq, bk, bv);
        } else if (item < 866) {
            int rel = item - 482;
            do_proj(1, rel / 64, rel % 64, sm, bq, bk, bv);
        } else if (item < 1250) {
            int rel = item - 866;
            do_proj(2, rel / 64, rel % 64, sm, bq, bk, bv);
        } else {
            do_attn(item - 1250, sm, out);
        }

        if (item < NFLAGS) {
            __syncthreads();
            if (threadIdx.x == 0) setflag(&g_flags[item]);
        }
    }
}

// ---------------------------------------------------------------------------
extern "C" void kernel_launch(void* const* d_in, const int* in_sizes, int n_in,
                              void* d_out, int out_size)
{
    const float* inp  = (const float*)d_in[0];
    const float* mask = (const float*)d_in[1];
    const float* Wq   = (const float*)d_in[2];
    const float* bq   = (const float*)d_in[3];
    const float* Wk   = (const float*)d_in[4];
    const float* bk   = (const float*)d_in[5];
    const float* Wv   = (const float*)d_in[6];
    const float* bv   = (const float*)d_in[7];
    float* out = (float*)d_out;

    cudaFuncSetAttribute(mega_kernel,
                         cudaFuncAttributeMaxDynamicSharedMemorySize,
                         (int)PROJ_SMEM);

    zero_kernel<<<1, 256>>>();
    mega_kernel<<<296, 256, PROJ_SMEM>>>(inp, mask, Wq, bq, Wk, bk, Wv, bv, out);
}

// round 11
// speedup vs baseline: 1.1192x; 1.1192x over previous
#include <cuda_runtime.h>
#include <cuda_fp16.h>
#include <math.h>

#define BATCH 16
#define SEQ   512
#define EMB   768
#define HEADS 12
#define HDIM  64
#define ROWS  (BATCH*SEQ)          // 8192
#define BHN   (BATCH*HEADS)        // 192

// fp16 staging globals (natural layouts)
__device__ __half g_inph[ROWS*EMB];          // [m][k]
__device__ __half g_Wh[3*EMB*EMB];           // [w][k][n]
__device__ __half g_Qh[BHN*SEQ*HDIM];        // [bh][s][d], pre-scaled 0.125*log2(e)
__device__ __half g_Kh[BHN*SEQ*HDIM];        // [bh][j][d]  compacted keys
__device__ __half g_Vh[BHN*SEQ*HDIM];        // [bh][j][d]  compacted keys
__device__ int    g_srcs[BATCH*SEQ];         // compacted: global input row (b*512+s)
__device__ int    g_nk[BATCH];               // unmasked key count per batch

// ---------------------------------------------------------------------------
// helpers
// ---------------------------------------------------------------------------
__device__ __forceinline__ void mma16(float c[4],
                                      unsigned a0, unsigned a1, unsigned a2, unsigned a3,
                                      unsigned b0, unsigned b1) {
    asm volatile(
        "mma.sync.aligned.m16n8k16.row.col.f32.f16.f16.f32 "
        "{%0,%1,%2,%3}, {%4,%5,%6,%7}, {%8,%9}, {%0,%1,%2,%3};"
        : "+f"(c[0]), "+f"(c[1]), "+f"(c[2]), "+f"(c[3])
        : "r"(a0), "r"(a1), "r"(a2), "r"(a3), "r"(b0), "r"(b1));
}

__device__ __forceinline__ void ldm4(unsigned& r0, unsigned& r1,
                                     unsigned& r2, unsigned& r3, unsigned a) {
    asm volatile("ldmatrix.sync.aligned.m8n8.x4.shared.b16 {%0,%1,%2,%3}, [%4];"
                 : "=r"(r0), "=r"(r1), "=r"(r2), "=r"(r3) : "r"(a));
}
__device__ __forceinline__ void ldm4t(unsigned& r0, unsigned& r1,
                                      unsigned& r2, unsigned& r3, unsigned a) {
    asm volatile("ldmatrix.sync.aligned.m8n8.x4.trans.shared.b16 {%0,%1,%2,%3}, [%4];"
                 : "=r"(r0), "=r"(r1), "=r"(r2), "=r"(r3) : "r"(a));
}

__device__ __forceinline__ unsigned pkh2(float lo, float hi) {
    unsigned r;
    asm("cvt.rn.f16x2.f32 %0, %1, %2;" : "=r"(r) : "f"(hi), "f"(lo));
    return r;
}

__device__ __forceinline__ float ex2(float x) {
    float r;
    asm("ex2.approx.ftz.f32 %0, %1;" : "=f"(r) : "f"(x));
    return r;
}

__device__ __forceinline__ unsigned smem_u32(const void* p) {
    unsigned a;
    asm("{.reg .u64 t; cvta.to.shared.u64 t, %1; cvt.u32.u64 %0, t;}"
        : "=r"(a) : "l"(p));
    return a;
}

__device__ __forceinline__ void cpa16(unsigned dst, const void* src) {
    asm volatile("cp.async.ca.shared.global [%0], [%1], 16;" :: "r"(dst), "l"(src));
}
#define CP_COMMIT() asm volatile("cp.async.commit_group;" ::: "memory")
#define CP_WAIT(N)  asm volatile("cp.async.wait_group %0;" :: "n"(N) : "memory")

// ---------------------------------------------------------------------------
// merged setup kernel: compact (16 blocks) + cvt_w (1728) + cvt_inp (6144)
// ---------------------------------------------------------------------------
#define NB_CMP  16
#define NB_CVTW (3*576)            // EMB*EMB/4/256 per matrix = 576
#define NB_CVTA 6144               // ROWS*EMB/4/256
#define NB_SETUP (NB_CMP + NB_CVTW + NB_CVTA)

__global__ __launch_bounds__(256) void setup_kernel(
    const float* __restrict__ inp,  const float* __restrict__ mask,
    const float* __restrict__ Wq,   const float* __restrict__ Wk,
    const float* __restrict__ Wv)
{
    const int blk = blockIdx.x;
    const int tid = threadIdx.x;

    if (blk < NB_CMP) {
        // -- per-batch compaction of unmasked keys (mask==0 kept), 256 thr --
        const int b = blk;
        __shared__ int sc[512];
        int f0 = (mask[b*512 + tid]       == 0.0f) ? 1 : 0;
        int f1 = (mask[b*512 + 256 + tid] == 0.0f) ? 1 : 0;
        sc[tid] = f0; sc[tid + 256] = f1;
        __syncthreads();
        for (int off = 1; off < 512; off <<= 1) {
            int i0 = tid, i1 = tid + 256;
            int v0 = sc[i0] + ((i0 >= off) ? sc[i0 - off] : 0);
            int v1 = sc[i1] + ((i1 >= off) ? sc[i1 - off] : 0);
            __syncthreads();
            sc[i0] = v0; sc[i1] = v1;
            __syncthreads();
        }
        int nk = sc[511];
        if (f0) g_srcs[b*512 + sc[tid] - 1]       = b*512 + tid;
        if (f1) g_srcs[b*512 + sc[tid + 256] - 1] = b*512 + 256 + tid;
        if (tid >= nk)       g_srcs[b*512 + tid]       = b*512;
        if (tid + 256 >= nk) g_srcs[b*512 + 256 + tid] = b*512;
        if (tid == 0) g_nk[b] = nk;
    } else if (blk < NB_CMP + NB_CVTW) {
        // -- weight convert fp32 -> fp16 --
        const int rel = blk - NB_CMP;
        const int w = rel / 576;
        const float* W = (w == 0) ? Wq : (w == 1) ? Wk : Wv;
        int i = (rel % 576) * 256 + tid;         // float4 index within W
        float4 v = reinterpret_cast<const float4*>(W)[i];
        __half2* o = reinterpret_cast<__half2*>(g_Wh + (long)w*EMB*EMB) + i*2;
        o[0] = __floats2half2_rn(v.x, v.y);
        o[1] = __floats2half2_rn(v.z, v.w);
    } else {
        // -- input convert fp32 -> fp16 --
        int i = (blk - NB_CMP - NB_CVTW) * 256 + tid;   // float4 index
        float4 v = reinterpret_cast<const float4*>(inp)[i];
        __half2* o = reinterpret_cast<__half2*>(g_inph) + i*2;
        o[0] = __floats2half2_rn(v.x, v.y);
        o[1] = __floats2half2_rn(v.z, v.w);
    }
}

// ---------------------------------------------------------------------------
// Kernel 1: fused QKV projection, fp16 MMA + ldmatrix, cp.async pipeline.
// z=0: Q over all 8192 rows (y = m-tile). z=1/2: K/V over COMPACTED rows
// (y = b*4 + t, tile t covers compacted j in [t*128, t*128+128), early exit).
// ---------------------------------------------------------------------------
#define AH    72
#define ABUFH (128*AH)             // 9216 halves
#define BHS   136
#define BBUFH (64*BHS)             // 8704 halves
#define PROJ_SMEM ((2*ABUFH + 2*BBUFH)*2)   // 71680 B

__global__ __launch_bounds__(256, 2) void qkv_proj(
    const float* __restrict__ bq, const float* __restrict__ bk,
    const float* __restrict__ bv)
{
    const int z = blockIdx.z;
    const int y = blockIdx.y;
    int bb = 0, tt = 0, nkb = 0;
    if (z > 0) {
        bb = y >> 2; tt = y & 3;
        nkb = g_nk[bb];
        if (tt*128 >= nkb) return;
    }

    const __half* Wp = g_Wh + (long)z*EMB*EMB;
    const float* bias = (z == 0) ? bq : (z == 1) ? bk : bv;

    const int n0 = blockIdx.x * 128;
    const int tid  = threadIdx.x;
    const int lane = tid & 31;
    const int wid  = tid >> 5;
    const int wm = (wid & 1) * 64;
    const int wn = (wid >> 1) * 32;
    const int g  = lane >> 2;
    const int t  = lane & 3;
    const int l15  = lane & 15;
    const int l7   = lane & 7;
    const int hi16 = (lane >> 4) & 1;
    const int hi8  = (lane >> 3) & 1;

    extern __shared__ __half sh[];
    const unsigned sb = smem_u32(sh);
    __shared__ int s_idx[128];      // global input row per tile row

    if (tid < 128)
        s_idx[tid] = (z == 0) ? (y*128 + tid)
                              : g_srcs[bb*512 + tt*128 + tid];
    __syncthreads();

    const unsigned abase = sb + ((wm + l15)*AH + hi16*8)*2;
    const unsigned bbase = sb + 2*ABUFH*2 + ((l7 + hi8*8)*BHS + wn + hi16*8)*2;

    float acc[4][4][4];
    #pragma unroll
    for (int mi = 0; mi < 4; mi++)
        #pragma unroll
        for (int nj = 0; nj < 4; nj++)
            #pragma unroll
            for (int c = 0; c < 4; c++) acc[mi][nj][c] = 0.0f;

    #define ISSUE(IT, BUF) { \
        _Pragma("unroll") for (int i = 0; i < 4; i++) { \
            int f = tid + i*256; int r = f >> 3; int c8 = f & 7; \
            cpa16(sb + ((BUF)*ABUFH + r*AH + c8*8)*2, \
                  g_inph + (long)s_idx[r]*EMB + (IT)*64 + c8*8); } \
        _Pragma("unroll") for (int i = 0; i < 4; i++) { \
            int f = tid + i*256; int r = f >> 4; int c8 = f & 15; \
            cpa16(sb + (2*ABUFH + (BUF)*BBUFH + r*BHS + c8*8)*2, \
                  Wp + ((IT)*64 + r)*EMB + n0 + c8*8); } \
        CP_COMMIT(); }

    ISSUE(0, 0);
    ISSUE(1, 1);

    for (int it = 0; it < 12; it++) {
        if (it < 10) CP_WAIT(1); else CP_WAIT(0);
        __syncthreads();

        const int buf = it & 1;
        const unsigned ab = abase + buf*ABUFH*2;
        const unsigned bb2 = bbase + buf*BBUFH*2;

        #pragma unroll
        for (int s = 0; s < 4; s++) {
            unsigned a[4][4];
            #pragma unroll
            for (int mi = 0; mi < 4; mi++)
                ldm4(a[mi][0], a[mi][1], a[mi][2], a[mi][3],
                     ab + (mi*16*AH + s*16)*2);
            unsigned b[4][2];
            #pragma unroll
            for (int p = 0; p < 2; p++) {
                unsigned r0, r1, r2, r3;
                ldm4t(r0, r1, r2, r3, bb2 + (s*16*BHS + p*16)*2);
                b[2*p][0] = r0; b[2*p][1] = r1;
                b[2*p+1][0] = r2; b[2*p+1][1] = r3;
            }
            #pragma unroll
            for (int mi = 0; mi < 4; mi++)
                #pragma unroll
                for (int nj = 0; nj < 4; nj++)
                    mma16(acc[mi][nj], a[mi][0], a[mi][1], a[mi][2], a[mi][3],
                          b[nj][0], b[nj][1]);
        }

        if (it + 2 < 12) {
            __syncthreads();
            ISSUE(it + 2, buf);
        }
    }
    #undef ISSUE

    // Epilogue
    if (z == 0) {
        const float qs = 0.18033688f;   // 0.125 * log2(e)
        #pragma unroll
        for (int mi = 0; mi < 4; mi++) {
            #pragma unroll
            for (int nj = 0; nj < 4; nj++) {
                #pragma unroll
                for (int c = 0; c < 4; c++) {
                    int row = y*128 + wm + mi*16 + g + ((c >= 2) ? 8 : 0);
                    int n   = n0 + wn + nj*8 + 2*t + (c & 1);
                    int h = n >> 6, d = n & 63;
                    int b = row >> 9, s = row & 511;
                    float val = (acc[mi][nj][c] + bias[n]) * qs;
                    g_Qh[((long)(b*HEADS + h)*SEQ + s)*HDIM + d] = __float2half_rn(val);
                }
            }
        }
    } else {
        __half* outh = (z == 1) ? g_Kh : g_Vh;
        #pragma unroll
        for (int mi = 0; mi < 4; mi++) {
            #pragma unroll
            for (int nj = 0; nj < 4; nj++) {
                #pragma unroll
                for (int c = 0; c < 4; c++) {
                    int rloc = wm + mi*16 + g + ((c >= 2) ? 8 : 0);
                    int j = tt*128 + rloc;
                    if (j < nkb) {
                        int n = n0 + wn + nj*8 + 2*t + (c & 1);
                        int h = n >> 6, d = n & 63;
                        float val = acc[mi][nj][c] + bias[n];
                        outh[((long)(bb*HEADS + h)*SEQ + j)*HDIM + d] =
                            __float2half_rn(val);
                    }
                }
            }
        }
    }
}

// ---------------------------------------------------------------------------
// Kernel 2: flash attention over COMPACTED keys. nch = ceil(nk/64) chunks.
// ---------------------------------------------------------------------------
#define QH    72
#define QBUFH (128*QH)             // 9216
#define KH    72
#define KBUFH (64*KH)              // 4608
#define VH    72
#define VBUFH (64*VH)              // 4608
#define ATTN_SMEM ((QBUFH + 2*KBUFH + 2*VBUFH)*2)   // 55296 B

__global__ __launch_bounds__(256, 2) void attn_kernel(float* __restrict__ out)
{
    const int b  = blockIdx.z;
    const int h  = blockIdx.y;
    const int bh = b*HEADS + h;
    const int q0 = blockIdx.x * 128;
    const int tid  = threadIdx.x;
    const int lane = tid & 31;
    const int wid  = tid >> 5;
    const int wm = wid * 16;
    const int g  = lane >> 2;
    const int t  = lane & 3;
    const int l15  = lane & 15;
    const int l7   = lane & 7;
    const int hi16 = (lane >> 4) & 1;
    const int hi8  = (lane >> 3) & 1;

    const int nk  = g_nk[b];
    const int nch = (nk + 63) >> 6;

    extern __shared__ __half sh[];
    const unsigned sb = smem_u32(sh);

    const __half* Qg = g_Qh + (long)bh*SEQ*HDIM + (long)q0*HDIM;
    const __half* Kg = g_Kh + (long)bh*SEQ*HDIM;
    const __half* Vg = g_Vh + (long)bh*SEQ*HDIM;

    const unsigned qbase = sb + ((wm + l15)*QH + hi16*8)*2;
    const unsigned kbase = sb + QBUFH*2 + ((l7 + hi16*8)*KH + hi8*8)*2;
    const unsigned vbase = sb + (QBUFH + 2*KBUFH)*2 + ((l7 + hi8*8)*VH + hi16*8)*2;

    #define ISSUE_KV(KC, BUF) { \
        _Pragma("unroll") for (int i = 0; i < 2; i++) { \
            int f = tid + i*256; int r = f >> 3; int c8 = f & 7; \
            cpa16(sb + (QBUFH + (BUF)*KBUFH + r*KH + c8*8)*2, \
                  Kg + ((KC)*64 + r)*HDIM + c8*8); } \
        _Pragma("unroll") for (int i = 0; i < 2; i++) { \
            int f = tid + i*256; int r = f >> 3; int c8 = f & 7; \
            cpa16(sb + (QBUFH + 2*KBUFH + (BUF)*VBUFH + r*VH + c8*8)*2, \
                  Vg + ((KC)*64 + r)*HDIM + c8*8); } \
        CP_COMMIT(); }

    // Prologue: Q + chunk0 (group 0), chunk1 (group 1; harmless if nch==1).
    {
        #pragma unroll
        for (int i = 0; i < 4; i++) {
            int f = tid + i*256; int r = f >> 3; int c8 = f & 7;
            cpa16(sb + (r*QH + c8*8)*2, Qg + r*HDIM + c8*8);
        }
        ISSUE_KV(0, 0);
        ISSUE_KV(1, 1);
    }

    float oacc[8][4];
    #pragma unroll
    for (int dj = 0; dj < 8; dj++)
        #pragma unroll
        for (int c = 0; c < 4; c++) oacc[dj][c] = 0.0f;
    float l0 = 0.0f, l1 = 0.0f;
    const unsigned FULL = 0xffffffffu;

    for (int kc = 0; kc < nch; kc++) {
        if (kc + 2 < nch) CP_WAIT(1); else CP_WAIT(0);
        __syncthreads();

        const int buf = kc & 1;
        const unsigned kb = kbase + buf*KBUFH*2;
        const unsigned vb = vbase + buf*VBUFH*2;

        // ---- S' = Q K^T (Q pre-scaled by 0.125*log2e) ----
        float sacc[8][4];
        #pragma unroll
        for (int nj = 0; nj < 8; nj++)
            #pragma unroll
            for (int c = 0; c < 4; c++) sacc[nj][c] = 0.0f;

        #pragma unroll
        for (int s = 0; s < 4; s++) {
            unsigned a0, a1, a2, a3;
            ldm4(a0, a1, a2, a3, qbase + (s*16)*2);
            #pragma unroll
            for (int p = 0; p < 4; p++) {
                unsigned r0, r1, r2, r3;
                ldm4(r0, r1, r2, r3, kb + (p*16*KH + s*16)*2);
                mma16(sacc[2*p],   a0, a1, a2, a3, r0, r1);
                mma16(sacc[2*p+1], a0, a1, a2, a3, r2, r3);
            }
        }

        // ---- P = exp2(S'); tail chunk zeroes padded keys ----
        float rs0 = 0.0f, rs1 = 0.0f;
        if (kc + 1 == nch) {
            #pragma unroll
            for (int nj = 0; nj < 8; nj++) {
                int key = kc*64 + nj*8 + 2*t;
                float p0 = (key   < nk) ? ex2(sacc[nj][0]) : 0.0f;
                float p1 = (key+1 < nk) ? ex2(sacc[nj][1]) : 0.0f;
                float p2 = (key   < nk) ? ex2(sacc[nj][2]) : 0.0f;
                float p3 = (key+1 < nk) ? ex2(sacc[nj][3]) : 0.0f;
                sacc[nj][0] = p0; sacc[nj][1] = p1;
                sacc[nj][2] = p2; sacc[nj][3] = p3;
                rs0 += p0 + p1; rs1 += p2 + p3;
            }
        } else {
            #pragma unroll
            for (int nj = 0; nj < 8; nj++) {
                float p0 = ex2(sacc[nj][0]);
                float p1 = ex2(sacc[nj][1]);
                float p2 = ex2(sacc[nj][2]);
                float p3 = ex2(sacc[nj][3]);
                sacc[nj][0] = p0; sacc[nj][1] = p1;
                sacc[nj][2] = p2; sacc[nj][3] = p3;
                rs0 += p0 + p1; rs1 += p2 + p3;
            }
        }
        l0 += rs0;
        l1 += rs1;

        // ---- O += P V ----
        #pragma unroll
        for (int s = 0; s < 4; s++) {
            unsigned a0 = pkh2(sacc[2*s][0],   sacc[2*s][1]);
            unsigned a1 = pkh2(sacc[2*s][2],   sacc[2*s][3]);
            unsigned a2 = pkh2(sacc[2*s+1][0], sacc[2*s+1][1]);
            unsigned a3 = pkh2(sacc[2*s+1][2], sacc[2*s+1][3]);
            #pragma unroll
            for (int p = 0; p < 4; p++) {
                unsigned r0, r1, r2, r3;
                ldm4t(r0, r1, r2, r3, vb + (s*16*VH + p*16)*2);
                mma16(oacc[2*p],   a0, a1, a2, a3, r0, r1);
                mma16(oacc[2*p+1], a0, a1, a2, a3, r2, r3);
            }
        }

        if (kc + 2 < nch) {
            __syncthreads();
            ISSUE_KV(kc + 2, buf);
        }
    }
    #undef ISSUE_KV

    // ---- normalize and write out (B, S, H*D) ----
    l0 += __shfl_xor_sync(FULL, l0, 1);
    l0 += __shfl_xor_sync(FULL, l0, 2);
    l1 += __shfl_xor_sync(FULL, l1, 1);
    l1 += __shfl_xor_sync(FULL, l1, 2);
    float inv0 = 1.0f / l0;
    float inv1 = 1.0f / l1;

    const int qa = q0 + wm + g;
    const int qb = qa + 8;
    #pragma unroll
    for (int dj = 0; dj < 8; dj++) {
        int d = h*HDIM + dj*8 + 2*t;
        out[(b*SEQ + qa)*EMB + d]     = oacc[dj][0] * inv0;
        out[(b*SEQ + qa)*EMB + d + 1] = oacc[dj][1] * inv0;
        out[(b*SEQ + qb)*EMB + d]     = oacc[dj][2] * inv1;
        out[(b*SEQ + qb)*EMB + d + 1] = oacc[dj][3] * inv1;
    }
}

// ---------------------------------------------------------------------------
extern "C" void kernel_launch(void* const* d_in, const int* in_sizes, int n_in,
                              void* d_out, int out_size)
{
    const float* inp  = (const float*)d_in[0];
    const float* mask = (const float*)d_in[1];
    const float* Wq   = (const float*)d_in[2];
    const float* bq   = (const float*)d_in[3];
    const float* Wk   = (const float*)d_in[4];
    const float* bk   = (const float*)d_in[5];
    const float* Wv   = (const float*)d_in[6];
    const float* bv   = (const float*)d_in[7];
    float* out = (float*)d_out;

    cudaFuncSetAttribute(qkv_proj,
                         cudaFuncAttributeMaxDynamicSharedMemorySize,
                         (int)PROJ_SMEM);
    cudaFuncSetAttribute(attn_kernel,
                         cudaFuncAttributeMaxDynamicSharedMemorySize,
                         (int)ATTN_SMEM);

    setup_kernel<<<NB_SETUP, 256>>>(inp, mask, Wq, Wk, Wv);

    dim3 gproj(EMB/128, 64, 3);
    qkv_proj<<<gproj, 256, PROJ_SMEM>>>(bq, bk, bv);

    dim3 gattn(SEQ/128, HEADS, BATCH);
    attn_kernel<<<gattn, 256, ATTN_SMEM>>>(out);
}

// round 12
// speedup vs baseline: 1.3785x; 1.2317x over previous
#include <cuda_runtime.h>
#include <cuda_fp16.h>
#include <math.h>

#define BATCH 16
#define SEQ   512
#define EMB   768
#define HEADS 12
#define HDIM  64
#define ROWS  (BATCH*SEQ)          // 8192
#define BHN   (BATCH*HEADS)        // 192

// fp16 staging globals (natural layouts)
__device__ __half g_inph[ROWS*EMB];          // [m][k]
__device__ __half g_Wh[3*EMB*EMB];           // [w][k][n]
__device__ __half g_Qh[BHN*SEQ*HDIM];        // [bh][s][d], pre-scaled 0.125*log2(e)
__device__ __half g_Kh[BHN*SEQ*HDIM];        // [bh][j][d]  compacted keys
__device__ __half g_Vh[BHN*SEQ*HDIM];        // [bh][j][d]  compacted keys
__device__ int    g_srcs[BATCH*SEQ];         // compacted: global input row (b*512+s)
__device__ int    g_nk[BATCH];               // unmasked key count per batch

// ---------------------------------------------------------------------------
// helpers
// ---------------------------------------------------------------------------
__device__ __forceinline__ void mma16(float c[4],
                                      unsigned a0, unsigned a1, unsigned a2, unsigned a3,
                                      unsigned b0, unsigned b1) {
    asm volatile(
        "mma.sync.aligned.m16n8k16.row.col.f32.f16.f16.f32 "
        "{%0,%1,%2,%3}, {%4,%5,%6,%7}, {%8,%9}, {%0,%1,%2,%3};"
        : "+f"(c[0]), "+f"(c[1]), "+f"(c[2]), "+f"(c[3])
        : "r"(a0), "r"(a1), "r"(a2), "r"(a3), "r"(b0), "r"(b1));
}

__device__ __forceinline__ void ldm4(unsigned& r0, unsigned& r1,
                                     unsigned& r2, unsigned& r3, unsigned a) {
    asm volatile("ldmatrix.sync.aligned.m8n8.x4.shared.b16 {%0,%1,%2,%3}, [%4];"
                 : "=r"(r0), "=r"(r1), "=r"(r2), "=r"(r3) : "r"(a));
}
__device__ __forceinline__ void ldm4t(unsigned& r0, unsigned& r1,
                                      unsigned& r2, unsigned& r3, unsigned a) {
    asm volatile("ldmatrix.sync.aligned.m8n8.x4.trans.shared.b16 {%0,%1,%2,%3}, [%4];"
                 : "=r"(r0), "=r"(r1), "=r"(r2), "=r"(r3) : "r"(a));
}

__device__ __forceinline__ unsigned pkh2(float lo, float hi) {
    unsigned r;
    asm("cvt.rn.f16x2.f32 %0, %1, %2;" : "=r"(r) : "f"(hi), "f"(lo));
    return r;
}

__device__ __forceinline__ float ex2(float x) {
    float r;
    asm("ex2.approx.ftz.f32 %0, %1;" : "=f"(r) : "f"(x));
    return r;
}

__device__ __forceinline__ unsigned smem_u32(const void* p) {
    unsigned a;
    asm("{.reg .u64 t; cvta.to.shared.u64 t, %1; cvt.u32.u64 %0, t;}"
        : "=r"(a) : "l"(p));
    return a;
}

__device__ __forceinline__ void cpa16(unsigned dst, const void* src) {
    asm volatile("cp.async.ca.shared.global [%0], [%1], 16;" :: "r"(dst), "l"(src));
}
#define CP_COMMIT() asm volatile("cp.async.commit_group;" ::: "memory")
#define CP_WAIT(N)  asm volatile("cp.async.wait_group %0;" :: "n"(N) : "memory")

// ---------------------------------------------------------------------------
// merged setup kernel: compact (16 blocks) + cvt_w (1728) + cvt_inp (6144)
// ---------------------------------------------------------------------------
#define NB_CMP  16
#define NB_CVTW (3*576)
#define NB_CVTA 6144
#define NB_SETUP (NB_CMP + NB_CVTW + NB_CVTA)

__global__ __launch_bounds__(256) void setup_kernel(
    const float* __restrict__ inp,  const float* __restrict__ mask,
    const float* __restrict__ Wq,   const float* __restrict__ Wk,
    const float* __restrict__ Wv)
{
    const int blk = blockIdx.x;
    const int tid = threadIdx.x;

    if (blk < NB_CMP) {
        const int b = blk;
        __shared__ int sc[512];
        int f0 = (mask[b*512 + tid]       == 0.0f) ? 1 : 0;
        int f1 = (mask[b*512 + 256 + tid] == 0.0f) ? 1 : 0;
        sc[tid] = f0; sc[tid + 256] = f1;
        __syncthreads();
        for (int off = 1; off < 512; off <<= 1) {
            int i0 = tid, i1 = tid + 256;
            int v0 = sc[i0] + ((i0 >= off) ? sc[i0 - off] : 0);
            int v1 = sc[i1] + ((i1 >= off) ? sc[i1 - off] : 0);
            __syncthreads();
            sc[i0] = v0; sc[i1] = v1;
            __syncthreads();
        }
        int nk = sc[511];
        if (f0) g_srcs[b*512 + sc[tid] - 1]       = b*512 + tid;
        if (f1) g_srcs[b*512 + sc[tid + 256] - 1] = b*512 + 256 + tid;
        if (tid >= nk)       g_srcs[b*512 + tid]       = b*512;
        if (tid + 256 >= nk) g_srcs[b*512 + 256 + tid] = b*512;
        if (tid == 0) g_nk[b] = nk;
    } else if (blk < NB_CMP + NB_CVTW) {
        const int rel = blk - NB_CMP;
        const int w = rel / 576;
        const float* W = (w == 0) ? Wq : (w == 1) ? Wk : Wv;
        int i = (rel % 576) * 256 + tid;
        float4 v = reinterpret_cast<const float4*>(W)[i];
        __half2* o = reinterpret_cast<__half2*>(g_Wh + (long)w*EMB*EMB) + i*2;
        o[0] = __floats2half2_rn(v.x, v.y);
        o[1] = __floats2half2_rn(v.z, v.w);
    } else {
        int i = (blk - NB_CMP - NB_CVTW) * 256 + tid;
        float4 v = reinterpret_cast<const float4*>(inp)[i];
        __half2* o = reinterpret_cast<__half2*>(g_inph) + i*2;
        o[0] = __floats2half2_rn(v.x, v.y);
        o[1] = __floats2half2_rn(v.z, v.w);
    }
}

// ---------------------------------------------------------------------------
// Kernel 1: fused QKV projection. 128 threads, 4 warps of 64x64.
// CTA tile 128x128, K-step 64 (12 iters), cp.async double buffer.
// ---------------------------------------------------------------------------
#define AH    72
#define ABUFH (128*AH)             // 9216 halves
#define BHS   136
#define BBUFH (64*BHS)             // 8704 halves
#define PROJ_SMEM ((2*ABUFH + 2*BBUFH)*2)   // 71680 B

__global__ __launch_bounds__(128, 2) void qkv_proj(
    const float* __restrict__ bq, const float* __restrict__ bk,
    const float* __restrict__ bv)
{
    const int z = blockIdx.z;
    const int y = blockIdx.y;
    int bb = 0, tt = 0, nkb = 0;
    if (z > 0) {
        bb = y >> 2; tt = y & 3;
        nkb = g_nk[bb];
        if (tt*128 >= nkb) return;
    }

    const __half* Wp = g_Wh + (long)z*EMB*EMB;
    const float* bias = (z == 0) ? bq : (z == 1) ? bk : bv;

    const int n0 = blockIdx.x * 128;
    const int tid  = threadIdx.x;
    const int lane = tid & 31;
    const int wid  = tid >> 5;
    const int wm = (wid & 1) * 64;      // warp M offset (2 m-warps)
    const int wn = (wid >> 1) * 64;     // warp N offset (2 n-warps)
    const int g  = lane >> 2;
    const int t  = lane & 3;
    const int l15  = lane & 15;
    const int l7   = lane & 7;
    const int hi16 = (lane >> 4) & 1;
    const int hi8  = (lane >> 3) & 1;

    extern __shared__ __half sh[];
    const unsigned sb = smem_u32(sh);
    __shared__ int s_idx[128];

    if (tid < 128)
        s_idx[tid] = (z == 0) ? (y*128 + tid)
                              : g_srcs[bb*512 + tt*128 + tid];
    __syncthreads();

    const unsigned abase = sb + ((wm + l15)*AH + hi16*8)*2;
    const unsigned bbase = sb + 2*ABUFH*2 + ((l7 + hi8*8)*BHS + wn + hi16*8)*2;

    float acc[4][8][4];
    #pragma unroll
    for (int mi = 0; mi < 4; mi++)
        #pragma unroll
        for (int nj = 0; nj < 8; nj++)
            #pragma unroll
            for (int c = 0; c < 4; c++) acc[mi][nj][c] = 0.0f;

    #define ISSUE(IT, BUF) { \
        _Pragma("unroll") for (int i = 0; i < 8; i++) { \
            int f = tid + i*128; int r = f >> 3; int c8 = f & 7; \
            cpa16(sb + ((BUF)*ABUFH + r*AH + c8*8)*2, \
                  g_inph + (long)s_idx[r]*EMB + (IT)*64 + c8*8); } \
        _Pragma("unroll") for (int i = 0; i < 8; i++) { \
            int f = tid + i*128; int r = f >> 4; int c8 = f & 15; \
            cpa16(sb + (2*ABUFH + (BUF)*BBUFH + r*BHS + c8*8)*2, \
                  Wp + ((IT)*64 + r)*EMB + n0 + c8*8); } \
        CP_COMMIT(); }

    ISSUE(0, 0);
    ISSUE(1, 1);

    for (int it = 0; it < 12; it++) {
        if (it < 10) CP_WAIT(1); else CP_WAIT(0);
        __syncthreads();

        const int buf = it & 1;
        const unsigned ab = abase + buf*ABUFH*2;
        const unsigned bb2 = bbase + buf*BBUFH*2;

        #pragma unroll
        for (int s = 0; s < 4; s++) {
            unsigned a[4][4];
            #pragma unroll
            for (int mi = 0; mi < 4; mi++)
                ldm4(a[mi][0], a[mi][1], a[mi][2], a[mi][3],
                     ab + (mi*16*AH + s*16)*2);
            unsigned b[8][2];
            #pragma unroll
            for (int p = 0; p < 4; p++) {
                unsigned r0, r1, r2, r3;
                ldm4t(r0, r1, r2, r3, bb2 + (s*16*BHS + p*16)*2);
                b[2*p][0] = r0; b[2*p][1] = r1;
                b[2*p+1][0] = r2; b[2*p+1][1] = r3;
            }
            #pragma unroll
            for (int mi = 0; mi < 4; mi++)
                #pragma unroll
                for (int nj = 0; nj < 8; nj++)
                    mma16(acc[mi][nj], a[mi][0], a[mi][1], a[mi][2], a[mi][3],
                          b[nj][0], b[nj][1]);
        }

        if (it + 2 < 12) {
            __syncthreads();
            ISSUE(it + 2, buf);
        }
    }
    #undef ISSUE

    // Epilogue: half2 stores (n even, pairs within one head).
    if (z == 0) {
        const float qs = 0.18033688f;   // 0.125 * log2(e)
        #pragma unroll
        for (int mi = 0; mi < 4; mi++) {
            #pragma unroll
            for (int nj = 0; nj < 8; nj++) {
                int n = n0 + wn + nj*8 + 2*t;
                int h = n >> 6, d = n & 63;
                float b0v = bias[n], b1v = bias[n+1];
                int row = y*128 + wm + mi*16 + g;
                int b = row >> 9, s = row & 511;
                __half2* p0 = reinterpret_cast<__half2*>(
                    &g_Qh[((long)(b*HEADS + h)*SEQ + s)*HDIM + d]);
                *p0 = __floats2half2_rn((acc[mi][nj][0] + b0v)*qs,
                                        (acc[mi][nj][1] + b1v)*qs);
                int row2 = row + 8;
                int b2 = row2 >> 9, s2 = row2 & 511;
                __half2* p1 = reinterpret_cast<__half2*>(
                    &g_Qh[((long)(b2*HEADS + h)*SEQ + s2)*HDIM + d]);
                *p1 = __floats2half2_rn((acc[mi][nj][2] + b0v)*qs,
                                        (acc[mi][nj][3] + b1v)*qs);
            }
        }
    } else {
        __half* outh = (z == 1) ? g_Kh : g_Vh;
        #pragma unroll
        for (int mi = 0; mi < 4; mi++) {
            #pragma unroll
            for (int nj = 0; nj < 8; nj++) {
                int n = n0 + wn + nj*8 + 2*t;
                int h = n >> 6, d = n & 63;
                float b0v = bias[n], b1v = bias[n+1];
                int j0 = tt*128 + wm + mi*16 + g;
                if (j0 < nkb) {
                    __half2* p0 = reinterpret_cast<__half2*>(
                        &outh[((long)(bb*HEADS + h)*SEQ + j0)*HDIM + d]);
                    *p0 = __floats2half2_rn(acc[mi][nj][0] + b0v,
                                            acc[mi][nj][1] + b1v);
                }
                int j1 = j0 + 8;
                if (j1 < nkb) {
                    __half2* p1 = reinterpret_cast<__half2*>(
                        &outh[((long)(bb*HEADS + h)*SEQ + j1)*HDIM + d]);
                    *p1 = __floats2half2_rn(acc[mi][nj][2] + b0v,
                                            acc[mi][nj][3] + b1v);
                }
            }
        }
    }
}

// ---------------------------------------------------------------------------
// Kernel 2: flash attention over COMPACTED keys. 128 threads, 4 warps x 32
// query rows (2 m-frags each). K/V fragments shared across both m-frags.
// ---------------------------------------------------------------------------
#define QH    72
#define QBUFH (128*QH)             // 9216
#define KH    72
#define KBUFH (64*KH)              // 4608
#define VH    72
#define VBUFH (64*VH)              // 4608
#define ATTN_SMEM ((QBUFH + 2*KBUFH + 2*VBUFH)*2)   // 55296 B

__global__ __launch_bounds__(128, 2) void attn_kernel(float* __restrict__ out)
{
    const int b  = blockIdx.z;
    const int h  = blockIdx.y;
    const int bh = b*HEADS + h;
    const int q0 = blockIdx.x * 128;
    const int tid  = threadIdx.x;
    const int lane = tid & 31;
    const int wid  = tid >> 5;
    const int wm = wid * 32;           // warp covers 32 query rows
    const int g  = lane >> 2;
    const int t  = lane & 3;
    const int l15  = lane & 15;
    const int l7   = lane & 7;
    const int hi16 = (lane >> 4) & 1;
    const int hi8  = (lane >> 3) & 1;

    const int nk  = g_nk[b];
    const int nch = (nk + 63) >> 6;

    extern __shared__ __half sh[];
    const unsigned sb = smem_u32(sh);

    const __half* Qg = g_Qh + (long)bh*SEQ*HDIM + (long)q0*HDIM;
    const __half* Kg = g_Kh + (long)bh*SEQ*HDIM;
    const __half* Vg = g_Vh + (long)bh*SEQ*HDIM;

    const unsigned qbase = sb + ((wm + l15)*QH + hi16*8)*2;
    const unsigned kbase = sb + QBUFH*2 + ((l7 + hi16*8)*KH + hi8*8)*2;
    const unsigned vbase = sb + (QBUFH + 2*KBUFH)*2 + ((l7 + hi8*8)*VH + hi16*8)*2;

    #define ISSUE_KV(KC, BUF) { \
        _Pragma("unroll") for (int i = 0; i < 4; i++) { \
            int f = tid + i*128; int r = f >> 3; int c8 = f & 7; \
            cpa16(sb + (QBUFH + (BUF)*KBUFH + r*KH + c8*8)*2, \
                  Kg + ((KC)*64 + r)*HDIM + c8*8); } \
        _Pragma("unroll") for (int i = 0; i < 4; i++) { \
            int f = tid + i*128; int r = f >> 3; int c8 = f & 7; \
            cpa16(sb + (QBUFH + 2*KBUFH + (BUF)*VBUFH + r*VH + c8*8)*2, \
                  Vg + ((KC)*64 + r)*HDIM + c8*8); } \
        CP_COMMIT(); }

    // Prologue: Q + chunk0 (group 0), chunk1 (group 1).
    {
        #pragma unroll
        for (int i = 0; i < 8; i++) {
            int f = tid + i*128; int r = f >> 3; int c8 = f & 7;
            cpa16(sb + (r*QH + c8*8)*2, Qg + r*HDIM + c8*8);
        }
        ISSUE_KV(0, 0);
        ISSUE_KV(1, 1);
    }

    float oacc[2][8][4];
    #pragma unroll
    for (int mh = 0; mh < 2; mh++)
        #pragma unroll
        for (int dj = 0; dj < 8; dj++)
            #pragma unroll
            for (int c = 0; c < 4; c++) oacc[mh][dj][c] = 0.0f;
    float lm[2][2] = {{0.0f, 0.0f}, {0.0f, 0.0f}};
    const unsigned FULL = 0xffffffffu;

    for (int kc = 0; kc < nch; kc++) {
        if (kc + 2 < nch) CP_WAIT(1); else CP_WAIT(0);
        __syncthreads();

        const int buf = kc & 1;
        const unsigned kb = kbase + buf*KBUFH*2;
        const unsigned vb = vbase + buf*VBUFH*2;

        // ---- S' = Q K^T (Q pre-scaled by 0.125*log2e) ----
        float sacc[2][8][4];
        #pragma unroll
        for (int mh = 0; mh < 2; mh++)
            #pragma unroll
            for (int nj = 0; nj < 8; nj++)
                #pragma unroll
                for (int c = 0; c < 4; c++) sacc[mh][nj][c] = 0.0f;

        #pragma unroll
        for (int s = 0; s < 4; s++) {
            unsigned kr[16];
            #pragma unroll
            for (int p = 0; p < 4; p++)
                ldm4(kr[4*p], kr[4*p+1], kr[4*p+2], kr[4*p+3],
                     kb + (p*16*KH + s*16)*2);
            #pragma unroll
            for (int mh = 0; mh < 2; mh++) {
                unsigned a0, a1, a2, a3;
                ldm4(a0, a1, a2, a3, qbase + (mh*16*QH + s*16)*2);
                #pragma unroll
                for (int p = 0; p < 4; p++) {
                    mma16(sacc[mh][2*p],   a0, a1, a2, a3, kr[4*p],   kr[4*p+1]);
                    mma16(sacc[mh][2*p+1], a0, a1, a2, a3, kr[4*p+2], kr[4*p+3]);
                }
            }
        }

        // ---- P = exp2(S'); tail chunk zeroes padded keys ----
        #pragma unroll
        for (int mh = 0; mh < 2; mh++) {
            float rs0 = 0.0f, rs1 = 0.0f;
            if (kc + 1 == nch) {
                #pragma unroll
                for (int nj = 0; nj < 8; nj++) {
                    int key = kc*64 + nj*8 + 2*t;
                    float p0 = (key   < nk) ? ex2(sacc[mh][nj][0]) : 0.0f;
                    float p1 = (key+1 < nk) ? ex2(sacc[mh][nj][1]) : 0.0f;
                    float p2 = (key   < nk) ? ex2(sacc[mh][nj][2]) : 0.0f;
                    float p3 = (key+1 < nk) ? ex2(sacc[mh][nj][3]) : 0.0f;
                    sacc[mh][nj][0] = p0; sacc[mh][nj][1] = p1;
                    sacc[mh][nj][2] = p2; sacc[mh][nj][3] = p3;
                    rs0 += p0 + p1; rs1 += p2 + p3;
                }
            } else {
                #pragma unroll
                for (int nj = 0; nj < 8; nj++) {
                    float p0 = ex2(sacc[mh][nj][0]);
                    float p1 = ex2(sacc[mh][nj][1]);
                    float p2 = ex2(sacc[mh][nj][2]);
                    float p3 = ex2(sacc[mh][nj][3]);
                    sacc[mh][nj][0] = p0; sacc[mh][nj][1] = p1;
                    sacc[mh][nj][2] = p2; sacc[mh][nj][3] = p3;
                    rs0 += p0 + p1; rs1 += p2 + p3;
                }
            }
            lm[mh][0] += rs0;
            lm[mh][1] += rs1;
        }

        // ---- O += P V ----
        #pragma unroll
        for (int s = 0; s < 4; s++) {
            unsigned vr[16];
            #pragma unroll
            for (int p = 0; p < 4; p++)
                ldm4t(vr[4*p], vr[4*p+1], vr[4*p+2], vr[4*p+3],
                      vb + (s*16*VH + p*16)*2);
            #pragma unroll
            for (int mh = 0; mh < 2; mh++) {
                unsigned a0 = pkh2(sacc[mh][2*s][0],   sacc[mh][2*s][1]);
                unsigned a1 = pkh2(sacc[mh][2*s][2],   sacc[mh][2*s][3]);
                unsigned a2 = pkh2(sacc[mh][2*s+1][0], sacc[mh][2*s+1][1]);
                unsigned a3 = pkh2(sacc[mh][2*s+1][2], sacc[mh][2*s+1][3]);
                #pragma unroll
                for (int p = 0; p < 4; p++) {
                    mma16(oacc[mh][2*p],   a0, a1, a2, a3, vr[4*p],   vr[4*p+1]);
                    mma16(oacc[mh][2*p+1], a0, a1, a2, a3, vr[4*p+2], vr[4*p+3]);
                }
            }
        }

        if (kc + 2 < nch) {
            __syncthreads();
            ISSUE_KV(kc + 2, buf);
        }
    }
    #undef ISSUE_KV

    // ---- normalize and write out (B, S, H*D), float2 stores ----
    #pragma unroll
    for (int mh = 0; mh < 2; mh++) {
        float la = lm[mh][0], lb = lm[mh][1];
        la += __shfl_xor_sync(FULL, la, 1);
        la += __shfl_xor_sync(FULL, la, 2);
        lb += __shfl_xor_sync(FULL, lb, 1);
        lb += __shfl_xor_sync(FULL, lb, 2);
        float inv0 = 1.0f / la;
        float inv1 = 1.0f / lb;

        const int qa = q0 + wm + mh*16 + g;
        const int qb = qa + 8;
        #pragma unroll
        for (int dj = 0; dj < 8; dj++) {
            int d = h*HDIM + dj*8 + 2*t;
            float2 v0 = make_float2(oacc[mh][dj][0]*inv0, oacc[mh][dj][1]*inv0);
            float2 v1 = make_float2(oacc[mh][dj][2]*inv1, oacc[mh][dj][3]*inv1);
            *reinterpret_cast<float2*>(&out[(b*SEQ + qa)*EMB + d]) = v0;
            *reinterpret_cast<float2*>(&out[(b*SEQ + qb)*EMB + d]) = v1;
        }
    }
}

// ---------------------------------------------------------------------------
extern "C" void kernel_launch(void* const* d_in, const int* in_sizes, int n_in,
                              void* d_out, int out_size)
{
    const float* inp  = (const float*)d_in[0];
    const float* mask = (const float*)d_in[1];
    const float* Wq   = (const float*)d_in[2];
    const float* bq   = (const float*)d_in[3];
    const float* Wk   = (const float*)d_in[4];
    const float* bk   = (const float*)d_in[5];
    const float* Wv   = (const float*)d_in[6];
    const float* bv   = (const float*)d_in[7];
    float* out = (float*)d_out;

    cudaFuncSetAttribute(qkv_proj,
                         cudaFuncAttributeMaxDynamicSharedMemorySize,
                         (int)PROJ_SMEM);
    cudaFuncSetAttribute(attn_kernel,
                         cudaFuncAttributeMaxDynamicSharedMemorySize,
                         (int)ATTN_SMEM);

    setup_kernel<<<NB_SETUP, 256>>>(inp, mask, Wq, Wk, Wv);

    dim3 gproj(EMB/128, 64, 3);
    qkv_proj<<<gproj, 128, PROJ_SMEM>>>(bq, bk, bv);

    dim3 gattn(SEQ/128, HEADS, BATCH);
    attn_kernel<<<gattn, 128, ATTN_SMEM>>>(out);
}